// round 3
// baseline (speedup 1.0000x reference)
#include <cuda_runtime.h>
#include <cstdint>

#define NH       4096
#define NH4      1024
#define OBS      512
#define NSTEPS   63
#define NOUT     128
#define CMB      4608
#define CMB4     1152

#define GRID     147
#define NW       7                    // warps per CTA
#define NTHREADS (NW * 32)            // 224
#define RPB      28                   // rows per CTA (4 per warp)
#define SW       14                   // weight rows cached in SMEM (rows 4w+1, 4w+2)

// dynamic smem: [SW rows of Wf fp32][64 dt values]  = 229,632 B (< 232,448 cap)
#define SMEM_FLOATS (SW * NH + 64)
#define SMEM_BYTES  (SMEM_FLOATS * 4)

__device__ __align__(16) float gV[2][NH];   // stage-input ping-pong
__device__ __align__(16) float gHn[NH];     // h_new
__device__ unsigned g_arrive;
__device__ volatile unsigned g_gen;

__device__ __forceinline__ void grid_sync() {
    __syncthreads();
    if (threadIdx.x == 0) {
        __threadfence();
        unsigned gen = g_gen;
        unsigned a = atomicAdd(&g_arrive, 1u);
        if (a == GRID - 1) {
            g_arrive = 0;
            __threadfence();
            g_gen = gen + 1;
        } else {
            while (g_gen == gen) { }
            __threadfence();
        }
    }
    __syncthreads();
}

__device__ __forceinline__ float warp_sum(float v) {
    #pragma unroll
    for (int o = 16; o; o >>= 1) v += __shfl_xor_sync(0xffffffffu, v, o);
    return v;
}

#define FMA4(A, Q, B) \
    { (A).x = fmaf((Q).x, (B).x, (A).x); (A).y = fmaf((Q).y, (B).y, (A).y); \
      (A).z = fmaf((Q).z, (B).z, (A).z); (A).w = fmaf((Q).w, (B).w, (A).w); }

__global__ void __launch_bounds__(NTHREADS, 1)
ode_rnn_kernel(const float* __restrict__ x,
               const float* __restrict__ h0,
               const float* __restrict__ t,
               const float* __restrict__ Wf,
               const float* __restrict__ bf,
               const float* __restrict__ Wi,
               const float* __restrict__ bi,
               const float* __restrict__ Wo,
               const float* __restrict__ bo,
               float* __restrict__ out)
{
    extern __shared__ float smem[];
    float4* wsm   = (float4*)smem;               // SW * NH4 float4
    float*  dtbuf = smem + SW * NH;              // 64 floats

    const int tid  = threadIdx.x;
    const int w    = tid >> 5;
    const int lane = tid & 31;
    const int base = blockIdx.x * RPB;

    // warp w owns rows r0..r0+3, r0 = base + 4w
    const int r0 = base + 4 * w;
    const int c0 = min(r0,     NH - 1);
    const int c3 = min(r0 + 3, NH - 1);

    const float4* Wf4 = (const float4*)Wf;

    // ---- SMEM preload: rows 4w+1 (slot 2w) and 4w+2 (slot 2w+1), all warps ----
    for (int idx = tid; idx < SW * NH4; idx += NTHREADS) {
        int slot   = idx >> 10;
        int within = idx & 1023;
        int lr     = ((slot >> 1) << 2) + 1 + (slot & 1);
        int gr     = min(base + lr, NH - 1);
        wsm[idx]   = __ldg(Wf4 + (size_t)gr * NH4 + within);
    }
    // dt table
    if (tid < NSTEPS) dtbuf[tid] = __ldg(t + tid + 1) - __ldg(t + tid);

    // ---- register cache: full row r0 per warp ----
    float4 wreg[32];
    {
        const float4* p = Wf4 + (size_t)c0 * NH4 + lane;
        #pragma unroll
        for (int k = 0; k < 32; ++k) wreg[k] = __ldg(p + 32 * k);
    }

    // per-lane RK4 state: lane j (<4) owns row r0+j
    float hh = 0.f, bfv = 0.f;
    if (lane < 4) {
        int r = min(r0 + lane, NH - 1);
        hh  = __ldg(h0 + r);
        bfv = __ldg(bf + r);
        if (r0 + lane < NH) gV[0][r0 + lane] = hh;
    }

    const float4* ws1 = wsm + (size_t)(2 * w)     * NH4;   // row r0+1 (SMEM)
    const float4* ws2 = wsm + (size_t)(2 * w + 1) * NH4;   // row r0+2 (SMEM)
    const float4* wg3 = Wf4 + (size_t)c3 * NH4;            // row r0+3 (L2)

    int p = 0;
    grid_sync();   // gV[0] complete, smem loaded everywhere

    float k1 = 0.f, k2 = 0.f, k3 = 0.f;

    for (int s = 0; s < NSTEPS; ++s) {
        const float dt   = dtbuf[s];
        const float half = 0.5f * dt;

        #pragma unroll 1
        for (int u = 0; u < 4; ++u) {
            const float4* vsrc = (const float4*)gV[p];

            // 4-deep prefetch rings for v (L2, coherent) and weight row3 (L2)
            float4 vr[4], w3[4];
            #pragma unroll
            for (int j = 0; j < 4; ++j) {
                vr[j] = __ldcg(vsrc + lane + 32 * j);
                w3[j] = __ldg (wg3  + lane + 32 * j);
            }

            float4 A0 = make_float4(0.f,0.f,0.f,0.f);
            float4 A1 = A0, A2 = A0, A3 = A0;

            #pragma unroll
            for (int k = 0; k < 32; ++k) {
                const int i = lane + 32 * k;
                float4 b  = vr[k & 3];
                float4 q3 = w3[k & 3];
                if (k < 28) {
                    vr[k & 3] = __ldcg(vsrc + i + 128);   // +32*4 float4
                    w3[k & 3] = __ldg (wg3  + i + 128);
                }
                float4 q1 = ws1[i];
                float4 q2 = ws2[i];
                FMA4(A0, wreg[k], b);
                FMA4(A1, q1, b);
                FMA4(A2, q2, b);
                FMA4(A3, q3, b);
            }

            float z0 = warp_sum((A0.x + A0.y) + (A0.z + A0.w));
            float z1 = warp_sum((A1.x + A1.y) + (A1.z + A1.w));
            float z2 = warp_sum((A2.x + A2.y) + (A2.z + A2.w));
            float z3 = warp_sum((A3.x + A3.y) + (A3.z + A3.w));

            float z  = (lane == 0) ? z0 : (lane == 1) ? z1 : (lane == 2) ? z2 : z3;
            float kk = tanhf(z + bfv);

            float vn;
            if (u == 0)      { k1 = kk; vn = hh + half * kk; }
            else if (u == 1) { k2 = kk; vn = hh + half * kk; }
            else if (u == 2) { k3 = kk; vn = hh + dt * kk; }
            else {
                hh = hh + (dt * (1.0f / 6.0f)) * (k1 + 2.0f * k2 + 2.0f * k3 + kk);
                vn = hh;
            }
            if (lane < 4 && (r0 + lane) < NH) gV[p ^ 1][r0 + lane] = vn;

            grid_sync();
            p ^= 1;
        }
    }
    // gV[p] == hT

    // ---- i2h: h_new = tanh(W_i2h @ [x; hT] + b_i2h) ----
    {
        float4* cmb = (float4*)smem;                 // reuse weight SMEM
        const float4* xs = (const float4*)x;
        const float4* hs = (const float4*)gV[p];
        for (int i = tid; i < CMB4; i += NTHREADS)
            cmb[i] = (i < OBS / 4) ? __ldg(xs + i) : __ldcg(hs + (i - OBS / 4));
        __syncthreads();

        const float4* Wi4 = (const float4*)Wi;
        const float4* p0 = Wi4 + (size_t)c0 * CMB4;
        const float4* p1 = Wi4 + (size_t)min(r0 + 1, NH - 1) * CMB4;
        const float4* p2 = Wi4 + (size_t)min(r0 + 2, NH - 1) * CMB4;
        const float4* p3 = Wi4 + (size_t)c3 * CMB4;

        float4 A0 = make_float4(0.f,0.f,0.f,0.f);
        float4 A1 = A0, A2 = A0, A3 = A0;
        #pragma unroll 4
        for (int k = 0; k < 36; ++k) {               // CMB4/32 = 36
            const int i = lane + 32 * k;
            float4 b = cmb[i];
            FMA4(A0, __ldg(p0 + i), b);
            FMA4(A1, __ldg(p1 + i), b);
            FMA4(A2, __ldg(p2 + i), b);
            FMA4(A3, __ldg(p3 + i), b);
        }
        float z0 = warp_sum((A0.x + A0.y) + (A0.z + A0.w));
        float z1 = warp_sum((A1.x + A1.y) + (A1.z + A1.w));
        float z2 = warp_sum((A2.x + A2.y) + (A2.z + A2.w));
        float z3 = warp_sum((A3.x + A3.y) + (A3.z + A3.w));

        if (lane < 4) {
            int r = r0 + lane;
            if (r < NH) {
                float z  = (lane == 0) ? z0 : (lane == 1) ? z1 : (lane == 2) ? z2 : z3;
                float hn = tanhf(z + __ldg(bi + r));
                gHn[r] = hn;
                out[NOUT + r] = hn;
            }
        }
    }
    grid_sync();

    // ---- h2o: out[0..127] = W_h2o @ h_new + b_h2o (one row per warp) ----
    {
        const int gw = blockIdx.x * NW + w;
        if (gw < NOUT) {
            const float4* wr = (const float4*)Wo + (size_t)gw * NH4;
            const float4* hv = (const float4*)gHn;
            float4 A = make_float4(0.f,0.f,0.f,0.f);
            #pragma unroll 4
            for (int k = 0; k < 32; ++k) {
                const int i = lane + 32 * k;
                FMA4(A, __ldg(wr + i), __ldcg(hv + i));
            }
            float z = warp_sum((A.x + A.y) + (A.z + A.w));
            if (lane == 0) out[gw] = z + __ldg(bo + gw);
        }
    }
}

extern "C" void kernel_launch(void* const* d_in, const int* in_sizes, int n_in,
                              void* d_out, int out_size)
{
    const float* x   = (const float*)d_in[0];
    const float* h0  = (const float*)d_in[1];
    const float* t   = (const float*)d_in[2];
    const float* Wf  = (const float*)d_in[3];
    const float* bf  = (const float*)d_in[4];
    const float* Wi  = (const float*)d_in[5];
    const float* bi  = (const float*)d_in[6];
    const float* Wo  = (const float*)d_in[7];
    const float* bo  = (const float*)d_in[8];
    float* out = (float*)d_out;

    cudaFuncSetAttribute(ode_rnn_kernel,
                         cudaFuncAttributeMaxDynamicSharedMemorySize, SMEM_BYTES);
    ode_rnn_kernel<<<GRID, NTHREADS, SMEM_BYTES>>>(x, h0, t, Wf, bf, Wi, bi, Wo, bo, out);
}

// round 4
// speedup vs baseline: 1.0633x; 1.0633x over previous
#include <cuda_runtime.h>
#include <cstdint>

#define NH       4096
#define NH4      1024
#define OBS      512
#define NSTEPS   63
#define NOUT     128
#define CMB      4608
#define CMB4     1152

#define GRID     147
#define NW       14                   // warps per CTA
#define NTHREADS (NW * 32)            // 448
#define RPB      28                   // rows per CTA (2 per warp)
#define SW       13                   // weight rows cached in SMEM (row 2w for w<13)

// dynamic smem: [SW rows of Wf][v buffer NH][dt 64]  = 229,632 B (< 232,448 cap)
#define SMEM_FLOATS (SW * NH + NH + 64)
#define SMEM_BYTES  (SMEM_FLOATS * 4)

__device__ __align__(16) float gV[2][NH];   // stage-input ping-pong
__device__ __align__(16) float gHn[NH];     // h_new
__device__ unsigned g_arrive;               // monotonic across barriers AND replays
__device__ unsigned g_gen;                  // monotonic phase counter

// Monotonic grid barrier: phase = old_count / GRID. Replay-safe (never resets).
__device__ __forceinline__ void grid_sync() {
    __syncthreads();
    if (threadIdx.x == 0) {
        unsigned a;
        asm volatile("atom.add.release.gpu.u32 %0, [%1], 1;"
                     : "=r"(a) : "l"(&g_arrive) : "memory");
        unsigned phase  = a / GRID;
        unsigned target = phase + 1;
        if (a - phase * GRID == GRID - 1) {
            asm volatile("st.release.gpu.u32 [%0], %1;"
                         :: "l"(&g_gen), "r"(target) : "memory");
        } else {
            unsigned cur;
            do {
                asm volatile("ld.acquire.gpu.u32 %0, [%1];"
                             : "=r"(cur) : "l"(&g_gen) : "memory");
            } while ((int)(cur - target) < 0);
        }
    }
    __syncthreads();
}

__device__ __forceinline__ float warp_sum(float v) {
    #pragma unroll
    for (int o = 16; o; o >>= 1) v += __shfl_xor_sync(0xffffffffu, v, o);
    return v;
}

#define FMA4(A, Q, B) \
    { (A).x = fmaf((Q).x, (B).x, (A).x); (A).y = fmaf((Q).y, (B).y, (A).y); \
      (A).z = fmaf((Q).z, (B).z, (A).z); (A).w = fmaf((Q).w, (B).w, (A).w); }

__global__ void __launch_bounds__(NTHREADS, 1)
ode_rnn_kernel(const float* __restrict__ x,
               const float* __restrict__ h0,
               const float* __restrict__ t,
               const float* __restrict__ Wf,
               const float* __restrict__ bf,
               const float* __restrict__ Wi,
               const float* __restrict__ bi,
               const float* __restrict__ Wo,
               const float* __restrict__ bo,
               float* __restrict__ out)
{
    extern __shared__ float smem[];
    float4* wsm   = (float4*)smem;               // SW * NH4 float4 (weight rows)
    float4* vsm   = (float4*)(smem + SW * NH);   // NH4 float4 (stage vector)
    float*  dtbuf = smem + SW * NH + NH;         // 64 floats

    const int tid  = threadIdx.x;
    const int w    = tid >> 5;
    const int lane = tid & 31;
    const int base = blockIdx.x * RPB;

    // warp w owns rows rA = base+2w (SMEM for w<13), rB = base+2w+1 (L2)
    const int rA = base + 2 * w;
    const int rB = rA + 1;
    const int cA = min(rA, NH - 1);
    const int cB = min(rB, NH - 1);

    const float4* Wf4 = (const float4*)Wf;
    const float4* pA  = Wf4 + (size_t)cA * NH4;
    const float4* pB  = Wf4 + (size_t)cB * NH4;

    // ---- SMEM weight preload: rows base+2s for s=0..12 ----
    for (int idx = tid; idx < SW * NH4; idx += NTHREADS) {
        int slot   = idx >> 10;
        int within = idx & 1023;
        int gr     = min(base + 2 * slot, NH - 1);
        wsm[idx]   = __ldg(Wf4 + (size_t)gr * NH4 + within);
    }
    if (tid < NSTEPS) dtbuf[tid] = __ldg(t + tid + 1) - __ldg(t + tid);

    // small register cache: first quarter of rowB (k = 0..7)
    float4 cacheB[8];
    #pragma unroll
    for (int k = 0; k < 8; ++k) cacheB[k] = __ldg(pB + lane + 32 * k);

    // per-lane RK4 state: lane 0 -> rA, lane 1 -> rB
    float hh = 0.f, bfv = 0.f;
    if (lane < 2) {
        int r = min(rA + lane, NH - 1);
        hh  = __ldg(h0 + r);
        bfv = __ldg(bf + r);
        if (rA + lane < NH) gV[0][rA + lane] = hh;
    }

    const float4* waS = wsm + (size_t)w * NH4;   // smem rowA (w<13)

    int p = 0;
    grid_sync();   // gV[0] complete, smem loaded everywhere

    float k1 = 0.f, k2 = 0.f, k3 = 0.f;

    for (int s = 0; s < NSTEPS; ++s) {
        const float dt   = dtbuf[s];
        const float half = 0.5f * dt;

        #pragma unroll 1
        for (int u = 0; u < 4; ++u) {
            const float4* vsrc = (const float4*)gV[p];

            // prefetch ring for rowB (k = 8..11) — issue before v fill
            float4 rb[4];
            #pragma unroll
            for (int j = 0; j < 4; ++j)
                rb[j] = __ldg(pB + lane + 32 * (8 + j));

            // warp 13 also streams rowA from L2
            float4 ra[4];
            if (w == NW - 1) {
                #pragma unroll
                for (int j = 0; j < 4; ++j)
                    ra[j] = __ldg(pA + lane + 32 * j);
            }

            // cooperative v fill (coherent L2 reads)
            for (int i = tid; i < NH4; i += NTHREADS)
                vsm[i] = __ldcg(vsrc + i);
            __syncthreads();

            float4 A0 = make_float4(0.f,0.f,0.f,0.f);
            float4 A1 = A0;

            if (w < NW - 1) {
                #pragma unroll
                for (int k = 0; k < 8; ++k) {
                    const int i = lane + 32 * k;
                    float4 b = vsm[i];
                    FMA4(A0, waS[i], b);
                    FMA4(A1, cacheB[k], b);
                }
                #pragma unroll
                for (int k = 8; k < 32; ++k) {
                    const int i = lane + 32 * k;
                    float4 b = vsm[i];
                    float4 q = rb[k & 3];
                    if (k < 28) rb[k & 3] = __ldg(pB + i + 128);
                    FMA4(A0, waS[i], b);
                    FMA4(A1, q, b);
                }
            } else {
                #pragma unroll
                for (int k = 0; k < 8; ++k) {
                    const int i = lane + 32 * k;
                    float4 b  = vsm[i];
                    float4 qa = ra[k & 3];
                    ra[k & 3] = __ldg(pA + i + 128);
                    FMA4(A0, qa, b);
                    FMA4(A1, cacheB[k], b);
                }
                #pragma unroll
                for (int k = 8; k < 32; ++k) {
                    const int i = lane + 32 * k;
                    float4 b  = vsm[i];
                    float4 qa = ra[k & 3];
                    float4 qb = rb[k & 3];
                    if (k < 28) {
                        ra[k & 3] = __ldg(pA + i + 128);
                        rb[k & 3] = __ldg(pB + i + 128);
                    }
                    FMA4(A0, qa, b);
                    FMA4(A1, qb, b);
                }
            }

            float zA = warp_sum((A0.x + A0.y) + (A0.z + A0.w));
            float zB = warp_sum((A1.x + A1.y) + (A1.z + A1.w));

            float z  = (lane == 0) ? zA : zB;
            float kk = tanhf(z + bfv);

            float vn;
            if (u == 0)      { k1 = kk; vn = hh + half * kk; }
            else if (u == 1) { k2 = kk; vn = hh + half * kk; }
            else if (u == 2) { k3 = kk; vn = hh + dt * kk; }
            else {
                hh = hh + (dt * (1.0f / 6.0f)) * (k1 + 2.0f * k2 + 2.0f * k3 + kk);
                vn = hh;
            }
            if (lane < 2 && (rA + lane) < NH) gV[p ^ 1][rA + lane] = vn;

            grid_sync();
            p ^= 1;
        }
    }
    // gV[p] == hT

    // ---- i2h: h_new = tanh(W_i2h @ [x; hT] + b_i2h) ----
    {
        float4* cmb = (float4*)smem;                 // reuse weight SMEM
        const float4* xs = (const float4*)x;
        const float4* hs = (const float4*)gV[p];
        for (int i = tid; i < CMB4; i += NTHREADS)
            cmb[i] = (i < OBS / 4) ? __ldg(xs + i) : __ldcg(hs + (i - OBS / 4));
        __syncthreads();

        const float4* Wi4 = (const float4*)Wi;
        const float4* q0 = Wi4 + (size_t)cA * CMB4;
        const float4* q1 = Wi4 + (size_t)cB * CMB4;

        float4 A0 = make_float4(0.f,0.f,0.f,0.f);
        float4 A1 = A0;
        #pragma unroll 4
        for (int k = 0; k < 36; ++k) {               // CMB4/32 = 36
            const int i = lane + 32 * k;
            float4 b = cmb[i];
            FMA4(A0, __ldg(q0 + i), b);
            FMA4(A1, __ldg(q1 + i), b);
        }
        float zA = warp_sum((A0.x + A0.y) + (A0.z + A0.w));
        float zB = warp_sum((A1.x + A1.y) + (A1.z + A1.w));

        if (lane < 2) {
            int r = rA + lane;
            if (r < NH) {
                float z  = (lane == 0) ? zA : zB;
                float hn = tanhf(z + __ldg(bi + r));
                gHn[r] = hn;
                out[NOUT + r] = hn;
            }
        }
    }
    grid_sync();

    // ---- h2o: out[0..127] = W_h2o @ h_new + b_h2o (one row per warp) ----
    {
        const int gw = blockIdx.x * NW + w;
        if (gw < NOUT) {
            const float4* wr = (const float4*)Wo + (size_t)gw * NH4;
            const float4* hv = (const float4*)gHn;
            float4 A = make_float4(0.f,0.f,0.f,0.f);
            #pragma unroll 4
            for (int k = 0; k < 32; ++k) {
                const int i = lane + 32 * k;
                FMA4(A, __ldg(wr + i), __ldcg(hv + i));
            }
            float z = warp_sum((A.x + A.y) + (A.z + A.w));
            if (lane == 0) out[gw] = z + __ldg(bo + gw);
        }
    }
}

extern "C" void kernel_launch(void* const* d_in, const int* in_sizes, int n_in,
                              void* d_out, int out_size)
{
    const float* x   = (const float*)d_in[0];
    const float* h0  = (const float*)d_in[1];
    const float* t   = (const float*)d_in[2];
    const float* Wf  = (const float*)d_in[3];
    const float* bf  = (const float*)d_in[4];
    const float* Wi  = (const float*)d_in[5];
    const float* bi  = (const float*)d_in[6];
    const float* Wo  = (const float*)d_in[7];
    const float* bo  = (const float*)d_in[8];
    float* out = (float*)d_out;

    cudaFuncSetAttribute(ode_rnn_kernel,
                         cudaFuncAttributeMaxDynamicSharedMemorySize, SMEM_BYTES);
    ode_rnn_kernel<<<GRID, NTHREADS, SMEM_BYTES>>>(x, h0, t, Wf, bf, Wi, bi, Wo, bo, out);
}